// round 9
// baseline (speedup 1.0000x reference)
#include <cuda_runtime.h>
#include <cuda_fp16.h>

// BAHDANAUplus — R9 (= R8 resubmitted after infra failure):
// 16 lanes/sample, 2 samples/warp, 2 dims/lane (float2).
// Weights packed as half2 (dim-pairs) -> 36 fewer regs; depth-3 software
// pipeline (embedding gathers issued TWO iterations before use, covering
// DRAM-tier latency); __launch_bounds__(128,5) for 20 warps/SM.

#define FULLMASK 0xffffffffu

__global__ __launch_bounds__(128, 5) void bahdanau_kernel(
    const int*   __restrict__ group_inputs,
    const int*   __restrict__ item_inputs,
    const int*   __restrict__ members,
    const float* __restrict__ user_emb,
    const float* __restrict__ item_emb,
    const float* __restrict__ genres,
    const float* __restrict__ attn_W,
    const float* __restrict__ attn_b,
    const float* __restrict__ pred_W1,
    const float* __restrict__ pred_b1,
    const float* __restrict__ pred_W2,
    const float* __restrict__ pred_b2,
    float*       __restrict__ out,
    int n)
{
    const int lane = threadIdx.x & 31;
    const int sub  = lane & 15;          // position within the sample's 16-lane group
    const int half = lane >> 4;          // which sample of the pair
    const int wid  = threadIdx.x >> 5;
    const int gw   = blockIdx.x * 4 + wid;
    const int nwarp  = gridDim.x * 4;
    const int stride = nwarp * 2;        // samples consumed per iteration

    const int d0 = sub * 2;              // this lane's first dim

    // ---- attn_W packed: awh[seg][k] = (W[seg*32+d0][k], W[seg*32+d0+1][k]) ----
    __half2 awh[4][3];
    #pragma unroll
    for (int seg = 0; seg < 4; seg++) {
        const float2* p = (const float2*)(attn_W + (seg * 32 + d0) * 3);
        const float2 q0 = p[0], q1 = p[1], q2 = p[2];
        awh[seg][0] = __floats2half2_rn(q0.x, q1.y);
        awh[seg][1] = __floats2half2_rn(q0.y, q2.x);
        awh[seg][2] = __floats2half2_rn(q1.x, q2.y);
    }

    // ---- pred_W1 packed: w1h[seg][j] = (W1[seg*32+d0][j], W1[seg*32+d0+1][j]) ----
    __half2 w1h[3][8];
    #pragma unroll
    for (int seg = 0; seg < 3; seg++) {
        const float4* p0 = (const float4*)(pred_W1 + (seg * 32 + d0) * 8);
        const float4* p1 = (const float4*)(pred_W1 + (seg * 32 + d0 + 1) * 8);
        const float4 x0 = p0[0], x1 = p0[1];
        const float4 y0 = p1[0], y1 = p1[1];
        w1h[seg][0] = __floats2half2_rn(x0.x, y0.x);
        w1h[seg][1] = __floats2half2_rn(x0.y, y0.y);
        w1h[seg][2] = __floats2half2_rn(x0.z, y0.z);
        w1h[seg][3] = __floats2half2_rn(x0.w, y0.w);
        w1h[seg][4] = __floats2half2_rn(x1.x, y1.x);
        w1h[seg][5] = __floats2half2_rn(x1.y, y1.y);
        w1h[seg][6] = __floats2half2_rn(x1.z, y1.z);
        w1h[seg][7] = __floats2half2_rn(x1.w, y1.w);
    }

    const float ab0 = attn_b[0], ab1 = attn_b[1], ab2 = attn_b[2];
    const int   jm  = (lane >> 1) & 7;   // hidden unit owned after value-split
    const float b1j = pred_b1[jm];
    const float w2j = pred_W2[jm];
    const float b2  = pred_b2[0];

    const bool q3  = (lane & 8) != 0;
    const bool q2b = (lane & 4) != 0;
    const bool q1b = (lane & 2) != 0;

    const float2* ue = (const float2*)user_emb;   // 16 float2 per row
    const float2* ie = (const float2*)item_emb;   // 7 float2 per row
    const float2* ge = (const float2*)genres;     // 9 float2 per row

    int bc = gw * 2;                     // iteration base; my sample = bc + half
    if (bc >= n) return;

    // ---- prologue: fill 3-deep pipeline ----
    // sample i=0: indices + embeddings (ec)
    int  scur = bc + half;
    bool vC   = (scur < n);
    float2 ec0, ec1, ec2, eci;
    {
        const int sl = vC ? scur : 0;
        const int g  = group_inputs[sl];
        const int it = item_inputs[sl];
        const int m0 = members[3 * g + 0];
        const int m1 = members[3 * g + 1];
        const int m2 = members[3 * g + 2];
        ec0 = ue[m0 * 16 + sub];
        ec1 = ue[m1 * 16 + sub];
        ec2 = ue[m2 * 16 + sub];
        eci = (sub < 7) ? ie[it * 7 + sub] : ge[it * 9 + (sub - 7)];
    }

    // sample i=1: indices + embeddings (en)
    int  bn  = bc + stride;
    float2 en0, en1, en2v, eni;
    {
        const int sx = bn + half;
        const int sl = (sx < n) ? sx : 0;
        const int g  = group_inputs[sl];
        const int it = item_inputs[sl];
        const int m0 = members[3 * g + 0];
        const int m1 = members[3 * g + 1];
        const int m2 = members[3 * g + 2];
        en0  = ue[m0 * 16 + sub];
        en1  = ue[m1 * 16 + sub];
        en2v = ue[m2 * 16 + sub];
        eni  = (sub < 7) ? ie[it * 7 + sub] : ge[it * 9 + (sub - 7)];
    }

    // sample i=2: indices only
    int bq = bn + stride;
    int m2a, m2b, m2c, it2;
    {
        const int sx = bq + half;
        const int sl = (sx < n) ? sx : 0;
        const int g  = group_inputs[sl];
        it2 = item_inputs[sl];
        m2a = members[3 * g + 0];
        m2b = members[3 * g + 1];
        m2c = members[3 * g + 2];
    }

    for (;;) {
        // ---- stage 1: issue gathers for sample i+2 (consumed in 2 iters) ----
        const float2 ef0 = ue[m2a * 16 + sub];
        const float2 ef1 = ue[m2b * 16 + sub];
        const float2 ef2 = ue[m2c * 16 + sub];
        const float2 efi = (sub < 7) ? ie[it2 * 7 + sub] : ge[it2 * 9 + (sub - 7)];

        // ---- stage 2: prefetch index chain for sample i+3 ----
        const int br = bq + stride;
        int m3a, m3b, m3c, it3;
        {
            const int sx = br + half;
            const int sl = (sx < n) ? sx : 0;
            const int g  = group_inputs[sl];
            it3 = item_inputs[sl];
            m3a = members[3 * g + 0];
            m3b = members[3 * g + 1];
            m3c = members[3 * g + 2];
        }

        // ---- stage 3: compute current sample ----
        float v0, v1, v2;
        {
            const float2 w00 = __half22float2(awh[0][0]);
            const float2 w10 = __half22float2(awh[1][0]);
            const float2 w20 = __half22float2(awh[2][0]);
            const float2 w30 = __half22float2(awh[3][0]);
            v0 = ec0.x * w00.x + ec0.y * w00.y
               + ec1.x * w10.x + ec1.y * w10.y
               + ec2.x * w20.x + ec2.y * w20.y
               + eci.x * w30.x + eci.y * w30.y;
            const float2 w01 = __half22float2(awh[0][1]);
            const float2 w11 = __half22float2(awh[1][1]);
            const float2 w21 = __half22float2(awh[2][1]);
            const float2 w31 = __half22float2(awh[3][1]);
            v1 = ec0.x * w01.x + ec0.y * w01.y
               + ec1.x * w11.x + ec1.y * w11.y
               + ec2.x * w21.x + ec2.y * w21.y
               + eci.x * w31.x + eci.y * w31.y;
            const float2 w02 = __half22float2(awh[0][2]);
            const float2 w12 = __half22float2(awh[1][2]);
            const float2 w22 = __half22float2(awh[2][2]);
            const float2 w32 = __half22float2(awh[3][2]);
            v2 = ec0.x * w02.x + ec0.y * w02.y
               + ec1.x * w12.x + ec1.y * w12.y
               + ec2.x * w22.x + ec2.y * w22.y
               + eci.x * w32.x + eci.y * w32.y;
        }
        #pragma unroll
        for (int off = 8; off > 0; off >>= 1) {
            v0 += __shfl_xor_sync(FULLMASK, v0, off);
            v1 += __shfl_xor_sync(FULLMASK, v1, off);
            v2 += __shfl_xor_sync(FULLMASK, v2, off);
        }
        const float a0 = v0 + ab0;
        const float a1 = v1 + ab1;
        const float a2 = v2 + ab2;

        float2 gv, n0;
        gv.x = a0 * ec0.x + a1 * ec1.x + a2 * ec2.x;
        gv.y = a0 * ec0.y + a1 * ec1.y + a2 * ec2.y;
        n0.x = gv.x * eci.x;
        n0.y = gv.y * eci.y;

        float h[8];
        #pragma unroll
        for (int j = 0; j < 8; j++) {
            const float2 wa = __half22float2(w1h[0][j]);
            const float2 wb = __half22float2(w1h[1][j]);
            const float2 wc = __half22float2(w1h[2][j]);
            h[j] = n0.x * wa.x + n0.y * wa.y
                 + gv.x * wb.x + gv.y * wb.y
                 + eci.x * wc.x + eci.y * wc.y;
        }

        // Value-splitting reduce of 8 values over the 16-lane group.
        float t[4];
        #pragma unroll
        for (int k = 0; k < 4; k++) {               // off=8: 8 -> 4
            const float snd = q3 ? h[k] : h[k + 4];
            const float rcv = __shfl_xor_sync(FULLMASK, snd, 8);
            t[k] = (q3 ? h[k + 4] : h[k]) + rcv;
        }
        float u[2];
        #pragma unroll
        for (int k = 0; k < 2; k++) {               // off=4: 4 -> 2
            const float snd = q2b ? t[k] : t[k + 2];
            const float rcv = __shfl_xor_sync(FULLMASK, snd, 4);
            u[k] = (q2b ? t[k + 2] : t[k]) + rcv;
        }
        {
            const float snd = q1b ? u[0] : u[1];    // off=2: 2 -> 1
            const float rcv = __shfl_xor_sync(FULLMASK, snd, 2);
            u[0] = (q1b ? u[1] : u[0]) + rcv;
        }
        float hh = u[0] + __shfl_xor_sync(FULLMASK, u[0], 1);
        // hh = complete h_jm, jm = (lane>>1)&7 within this sample's group.

        float p = fmaxf(hh + b1j, 0.0f) * w2j;
        p += __shfl_xor_sync(FULLMASK, p, 2);       // orbit over lane bits 1..3
        p += __shfl_xor_sync(FULLMASK, p, 4);
        p += __shfl_xor_sync(FULLMASK, p, 8);

        const float y = __fdividef(1.0f, 1.0f + __expf(-(p + b2)));
        if (sub == 0 && vC) out[scur] = y;

        if (bn >= n) break;                          // nothing left anywhere

        // ---- rotate pipeline state ----
        bc = bn;  scur = bc + half;  vC = (scur < n);
        ec0 = en0; ec1 = en1; ec2 = en2v; eci = eni;
        en0 = ef0; en1 = ef1; en2v = ef2; eni = efi;
        bn = bq; bq = br;
        m2a = m3a; m2b = m3b; m2c = m3c; it2 = it3;
    }
}

extern "C" void kernel_launch(void* const* d_in, const int* in_sizes, int n_in,
                              void* d_out, int out_size)
{
    (void)n_in; (void)out_size;
    const int*   group_inputs = (const int*)  d_in[0];
    const int*   item_inputs  = (const int*)  d_in[1];
    const int*   members      = (const int*)  d_in[2];
    const float* user_emb     = (const float*)d_in[3];
    const float* item_emb     = (const float*)d_in[4];
    const float* genres       = (const float*)d_in[5];
    const float* attn_W       = (const float*)d_in[6];
    const float* attn_b       = (const float*)d_in[7];
    const float* pred_W1      = (const float*)d_in[8];
    const float* pred_b1      = (const float*)d_in[9];
    const float* pred_W2      = (const float*)d_in[10];
    const float* pred_b2      = (const float*)d_in[11];
    float* out = (float*)d_out;
    const int n = in_sizes[0];

    // 2048 blocks x 4 warps x 2 samples = 16384 slots -> 8 iterations each.
    const int blocks = 2048;
    bahdanau_kernel<<<blocks, 128>>>(group_inputs, item_inputs, members,
                                     user_emb, item_emb, genres,
                                     attn_W, attn_b, pred_W1, pred_b1,
                                     pred_W2, pred_b2, out, n);
}